// round 4
// baseline (speedup 1.0000x reference)
#include <cuda_runtime.h>
#include <math.h>

// Problem constants
#define KB 4
#define KN 4096
#define KM 4096
#define KC 256
#define KROWS (KB * KN)
#define NBINS 376
#define WCAP 256          // per-warp candidate capacity (expected ~10, max ~35)

// -------------------- device scratch (allocation-free) ---------------------
__device__ float  g_Q[KB * KN * KC];
__device__ float  g_K[KB * KM * KC];
__device__ float  g_V[KB * KM * KC];
__device__ float  g_MF[KB * KN * KC];
__device__ float2 g_bin_uv[KB * KM];
__device__ int    g_bin_idx[KB * KM];
__device__ int    g_bin_off[KB * (NBINS + 1)];

// ---------------------------------------------------------------------------
// v-bin CSR for kpts_R, one block per batch
// ---------------------------------------------------------------------------
__global__ void build_bins_kernel(const float* __restrict__ kptsR)
{
    const int b   = blockIdx.x;
    const int tid = threadIdx.x;
    __shared__ int cnt[NBINS];
    __shared__ int off[NBINS + 1];
    __shared__ int cur[NBINS];

    for (int i = tid; i < NBINS; i += blockDim.x) cnt[i] = 0;
    __syncthreads();

    const float* kR = kptsR + (size_t)b * KM * 2;
    for (int m = tid; m < KM; m += blockDim.x) {
        int bin = (int)kR[2 * m + 1];
        bin = max(0, min(NBINS - 1, bin));
        atomicAdd(&cnt[bin], 1);
    }
    __syncthreads();

    if (tid == 0) {
        off[0] = 0;
        for (int i = 0; i < NBINS; i++) off[i + 1] = off[i] + cnt[i];
    }
    __syncthreads();

    for (int i = tid; i < NBINS; i += blockDim.x) cur[i] = off[i];
    __syncthreads();

    for (int m = tid; m < KM; m += blockDim.x) {
        const float u = kR[2 * m];
        const float v = kR[2 * m + 1];
        int bin = max(0, min(NBINS - 1, (int)v));
        const int p = atomicAdd(&cur[bin], 1);
        g_bin_uv[(size_t)b * KM + p]  = make_float2(u, v);
        g_bin_idx[(size_t)b * KM + p] = m;
    }

    for (int i = tid; i <= NBINS; i += blockDim.x)
        g_bin_off[b * (NBINS + 1) + i] = off[i];
}

// ---------------------------------------------------------------------------
// tf32 tensor-core GEMM (NT + bias), cp.async double-buffered.
// 128x128x32 block tile, 8 warps (2m x 4n), warp tile 64x32.
// smem layout [m][BBK+4] floats; tf32 conversion on the LDS->reg path.
// ---------------------------------------------------------------------------
#define BM 128
#define BN 128
#define BBK 32
#define KPAD (BBK + 4)
#define NTILES (KC / BBK)      // 8
#define ABYTES (BM * KPAD * 4) // 18432 per buffer

__device__ __forceinline__ unsigned f2tf32(float x)
{
    unsigned u;
    asm("cvt.rna.tf32.f32 %0, %1;" : "=r"(u) : "f"(x));
    return u;
}

__device__ __forceinline__ void cp16(void* smem_dst, const void* gmem_src)
{
    unsigned s = (unsigned)__cvta_generic_to_shared(smem_dst);
    asm volatile("cp.async.cg.shared.global [%0], [%1], 16;"
                 :: "r"(s), "l"(gmem_src));
}

__device__ __forceinline__ void gemm_tf32_body(const float* __restrict__ A,
                                               const float* __restrict__ W,
                                               const float* __restrict__ bias,
                                               float* __restrict__ Cout)
{
    extern __shared__ char sm_raw[];
    float (*As)[BM][KPAD] = reinterpret_cast<float (*)[BM][KPAD]>(sm_raw);
    float (*Bs)[BM][KPAD] = reinterpret_cast<float (*)[BM][KPAD]>(sm_raw + 2 * ABYTES);

    const int row0 = blockIdx.y * BM;
    const int col0 = blockIdx.x * BN;
    const int tid  = threadIdx.x;
    const int warp = tid >> 5;
    const int lane = tid & 31;
    const int grp  = lane >> 2;      // 0..7
    const int tg   = lane & 3;       // 0..3
    const int wm   = (warp & 1) * 64;
    const int wn   = (warp >> 1) * 32;

    // per-thread copy coordinates (4 float4 per matrix per tile)
    int cr[4], ck[4];
#pragma unroll
    for (int j = 0; j < 4; j++) {
        const int e = tid + j * 256;
        cr[j] = e >> 3;
        ck[j] = (e & 7) * 4;
    }

    float acc[4][4][4];
#pragma unroll
    for (int mt = 0; mt < 4; mt++)
#pragma unroll
        for (int nt = 0; nt < 4; nt++)
#pragma unroll
            for (int e = 0; e < 4; e++) acc[mt][nt][e] = 0.0f;

    // prologue: tile 0 -> buf 0
#pragma unroll
    for (int j = 0; j < 4; j++) {
        cp16(&As[0][cr[j]][ck[j]], A + (size_t)(row0 + cr[j]) * KC + ck[j]);
        cp16(&Bs[0][cr[j]][ck[j]], W + (size_t)(col0 + cr[j]) * KC + ck[j]);
    }
    asm volatile("cp.async.commit_group;");

#pragma unroll
    for (int t = 0; t < NTILES; t++) {
        const int buf = t & 1;
        if (t + 1 < NTILES) {
            const int nb = (t + 1) & 1;
            const int k0 = (t + 1) * BBK;
#pragma unroll
            for (int j = 0; j < 4; j++) {
                cp16(&As[nb][cr[j]][ck[j]],
                     A + (size_t)(row0 + cr[j]) * KC + k0 + ck[j]);
                cp16(&Bs[nb][cr[j]][ck[j]],
                     W + (size_t)(col0 + cr[j]) * KC + k0 + ck[j]);
            }
            asm volatile("cp.async.commit_group;");
            asm volatile("cp.async.wait_group 1;");
        } else {
            asm volatile("cp.async.wait_group 0;");
        }
        __syncthreads();

#pragma unroll
        for (int ks = 0; ks < BBK; ks += 8) {
            unsigned a[4][4], b[4][2];
#pragma unroll
            for (int mt = 0; mt < 4; mt++) {
                const int m = wm + mt * 16 + grp;
                a[mt][0] = f2tf32(As[buf][m][ks + tg]);
                a[mt][1] = f2tf32(As[buf][m + 8][ks + tg]);
                a[mt][2] = f2tf32(As[buf][m][ks + tg + 4]);
                a[mt][3] = f2tf32(As[buf][m + 8][ks + tg + 4]);
            }
#pragma unroll
            for (int nt = 0; nt < 4; nt++) {
                const int n = wn + nt * 8 + grp;
                b[nt][0] = f2tf32(Bs[buf][n][ks + tg]);
                b[nt][1] = f2tf32(Bs[buf][n][ks + tg + 4]);
            }
#pragma unroll
            for (int mt = 0; mt < 4; mt++)
#pragma unroll
                for (int nt = 0; nt < 4; nt++)
                    asm volatile(
                        "mma.sync.aligned.m16n8k8.row.col.f32.tf32.tf32.f32 "
                        "{%0,%1,%2,%3}, {%4,%5,%6,%7}, {%8,%9}, {%0,%1,%2,%3};"
                        : "+f"(acc[mt][nt][0]), "+f"(acc[mt][nt][1]),
                          "+f"(acc[mt][nt][2]), "+f"(acc[mt][nt][3])
                        : "r"(a[mt][0]), "r"(a[mt][1]),
                          "r"(a[mt][2]), "r"(a[mt][3]),
                          "r"(b[nt][0]), "r"(b[nt][1]));
        }
        __syncthreads();
    }

#pragma unroll
    for (int mt = 0; mt < 4; mt++) {
        const int m = row0 + wm + mt * 16 + grp;
#pragma unroll
        for (int nt = 0; nt < 4; nt++) {
            const int n = col0 + wn + nt * 8 + 2 * tg;
            const float2 bv = *reinterpret_cast<const float2*>(bias + n);
            float2 o0, o1;
            o0.x = acc[mt][nt][0] + bv.x;
            o0.y = acc[mt][nt][1] + bv.y;
            o1.x = acc[mt][nt][2] + bv.x;
            o1.y = acc[mt][nt][3] + bv.y;
            *reinterpret_cast<float2*>(Cout + (size_t)m * KC + n)       = o0;
            *reinterpret_cast<float2*>(Cout + (size_t)(m + 8) * KC + n) = o1;
        }
    }
}

__global__ void __launch_bounds__(256)
gemm_qkv(const float* __restrict__ nodes_L, const float* __restrict__ nodes_R,
         const float* __restrict__ Wq, const float* __restrict__ bq,
         const float* __restrict__ Wk, const float* __restrict__ bk,
         const float* __restrict__ Wv, const float* __restrict__ bv,
         float* __restrict__ Q, float* __restrict__ K, float* __restrict__ V)
{
    const int z = blockIdx.z;
    const float* A    = (z == 0) ? nodes_L : nodes_R;
    const float* W    = (z == 0) ? Wq : (z == 1) ? Wk : Wv;
    const float* bias = (z == 0) ? bq : (z == 1) ? bk : bv;
    float*       C    = (z == 0) ? Q  : (z == 1) ? K  : V;
    gemm_tf32_body(A, W, bias, C);
}

__global__ void __launch_bounds__(256)
gemm_out(const float* __restrict__ A, const float* __restrict__ W,
         const float* __restrict__ bias, float* __restrict__ C)
{
    gemm_tf32_body(A, W, bias, C);
}

// ---------------------------------------------------------------------------
// Sparse epipolar attention — ONE WARP PER QUERY ROW. 8 warps/block.
// Warp-aggregated compaction, shfl reductions, no block barriers.
// ---------------------------------------------------------------------------
__global__ void __launch_bounds__(256)
attn_sparse_kernel(const float* __restrict__ kptsL,
                   const float* __restrict__ kptsR,
                   float* __restrict__ attn,
                   float* __restrict__ disp,
                   float* __restrict__ conf)
{
    __shared__ int   s_idx[8][WCAP];
    __shared__ float s_du[8][WCAP];
    __shared__ float s_sc[8][WCAP];

    const int wid  = threadIdx.x >> 5;
    const int lane = threadIdx.x & 31;
    const int row  = blockIdx.x * 8 + wid;
    const int b    = row >> 12;

    const float uL = kptsL[(size_t)row * 2 + 0];
    const float vL = kptsL[(size_t)row * 2 + 1];

    int lo = max((int)floorf(vL - 3.0f), 0);
    int hi = min((int)floorf(vL + 3.0f), NBINS - 1);
    const int* off   = g_bin_off + b * (NBINS + 1);
    const int  start = off[lo];
    const int  end   = off[hi + 1];

    // warp-aggregated compaction of valid candidates
    int cnt = 0;
    for (int j0 = start; j0 < end; j0 += 32) {
        const int j = j0 + lane;
        bool valid = false;
        float du = 0.0f;
        int idx = 0;
        if (j < end) {
            const float2 uv = g_bin_uv[(size_t)b * KM + j];
            du = uL - uv.x;
            valid = (fabsf(vL - uv.y) < 3.0f) && (du > 0.0f) && (du < 192.0f);
            if (valid) idx = g_bin_idx[(size_t)b * KM + j];
        }
        const unsigned ball = __ballot_sync(0xffffffffu, valid);
        const int pos = cnt + __popc(ball & ((1u << lane) - 1u));
        if (valid && pos < WCAP) {
            s_idx[wid][pos] = idx;
            s_du[wid][pos]  = du;
        }
        cnt += __popc(ball);
    }
    cnt = min(cnt, WCAP);
    __syncwarp();

    float* attn_row = attn + (size_t)row * KM;
    float4* ar4 = reinterpret_cast<float4*>(attn_row);

    if (cnt > 0) {
        // Q slice for this lane (channels 4*lane.. and 4*(lane+32)..)
        const float4* qg = reinterpret_cast<const float4*>(g_Q + (size_t)row * KC);
        const float4 qa = qg[lane];
        const float4 qb = qg[lane + 32];

        // scores: warp-per-candidate, serial over cnt (~10)
        const float* Kb = g_K + (size_t)b * KM * KC;
        for (int i = 0; i < cnt; i++) {
            const float4* k4 = reinterpret_cast<const float4*>(
                Kb + (size_t)s_idx[wid][i] * KC);
            const float4 ka = __ldg(k4 + lane);
            const float4 kb = __ldg(k4 + lane + 32);
            float sum = qa.x * ka.x + qa.y * ka.y + qa.z * ka.z + qa.w * ka.w
                      + qb.x * kb.x + qb.y * kb.y + qb.z * kb.z + qb.w * kb.w;
#pragma unroll
            for (int o = 16; o > 0; o >>= 1)
                sum += __shfl_xor_sync(0xffffffffu, sum, o);
            if (lane == 0) s_sc[wid][i] = sum * 0.0625f;   // 1/sqrt(256)
        }
        __syncwarp();

        // softmax (warp-level)
        float mx = -1e30f;
        for (int i = lane; i < cnt; i += 32) mx = fmaxf(mx, s_sc[wid][i]);
#pragma unroll
        for (int o = 16; o > 0; o >>= 1)
            mx = fmaxf(mx, __shfl_xor_sync(0xffffffffu, mx, o));

        float sm = 0.0f;
        for (int i = lane; i < cnt; i += 32) {
            const float e = expf(s_sc[wid][i] - mx);
            s_sc[wid][i] = e;
            sm += e;
        }
#pragma unroll
        for (int o = 16; o > 0; o >>= 1)
            sm += __shfl_xor_sync(0xffffffffu, sm, o);
        const float inv = 1.0f / sm;

        float dsum = 0.0f;
        for (int i = lane; i < cnt; i += 32) {
            const float w = s_sc[wid][i] * inv;
            s_sc[wid][i] = w;
            dsum += w * s_du[wid][i];
        }
#pragma unroll
        for (int o = 16; o > 0; o >>= 1)
            dsum += __shfl_xor_sync(0xffffffffu, dsum, o);
        __syncwarp();

        // attn row: zero-fill + scatter
        const float4 z4 = make_float4(0.f, 0.f, 0.f, 0.f);
#pragma unroll
        for (int t = 0; t < KM / 4 / 32; t++) ar4[lane + 32 * t] = z4;
        __syncwarp();
        for (int i = lane; i < cnt; i += 32) attn_row[s_idx[wid][i]] = s_sc[wid][i];

        // matched features: lane owns channels [8*lane, 8*lane+8)
        const float* Vb = g_V + (size_t)b * KM * KC;
        float4 a0 = z4, a1 = z4;
        for (int i = 0; i < cnt; i++) {
            const float w = s_sc[wid][i];
            const float4* v4 = reinterpret_cast<const float4*>(
                Vb + (size_t)s_idx[wid][i] * KC);
            const float4 va = __ldg(v4 + lane * 2);
            const float4 vb = __ldg(v4 + lane * 2 + 1);
            a0.x = fmaf(w, va.x, a0.x); a0.y = fmaf(w, va.y, a0.y);
            a0.z = fmaf(w, va.z, a0.z); a0.w = fmaf(w, va.w, a0.w);
            a1.x = fmaf(w, vb.x, a1.x); a1.y = fmaf(w, vb.y, a1.y);
            a1.z = fmaf(w, vb.z, a1.z); a1.w = fmaf(w, vb.w, a1.w);
        }
        float4* mf4 = reinterpret_cast<float4*>(g_MF + (size_t)row * KC);
        mf4[lane * 2]     = a0;
        mf4[lane * 2 + 1] = a1;

        if (lane == 0) { disp[row] = dsum; conf[row] = 1.0f; }
    } else {
        // fully-masked row: uniform 1/M softmax (exact)
        const float wu = 1.0f / (float)KM;
        const float4 w4 = make_float4(wu, wu, wu, wu);
#pragma unroll
        for (int t = 0; t < KM / 4 / 32; t++) ar4[lane + 32 * t] = w4;

        const float* Vb = g_V + (size_t)b * KM * KC;
        float4 a0 = make_float4(0.f, 0.f, 0.f, 0.f), a1 = a0;
#pragma unroll 4
        for (int m = 0; m < KM; m++) {
            const float4* v4 = reinterpret_cast<const float4*>(Vb + (size_t)m * KC);
            const float4 va = __ldg(v4 + lane * 2);
            const float4 vb = __ldg(v4 + lane * 2 + 1);
            a0.x += va.x; a0.y += va.y; a0.z += va.z; a0.w += va.w;
            a1.x += vb.x; a1.y += vb.y; a1.z += vb.z; a1.w += vb.w;
        }
        a0.x *= wu; a0.y *= wu; a0.z *= wu; a0.w *= wu;
        a1.x *= wu; a1.y *= wu; a1.z *= wu; a1.w *= wu;
        float4* mf4 = reinterpret_cast<float4*>(g_MF + (size_t)row * KC);
        mf4[lane * 2]     = a0;
        mf4[lane * 2 + 1] = a1;

        const float* kR = kptsR + (size_t)b * KM * 2;
        float su = 0.0f;
        for (int m = lane; m < KM; m += 32) su += kR[2 * m];
#pragma unroll
        for (int o = 16; o > 0; o >>= 1)
            su += __shfl_xor_sync(0xffffffffu, su, o);
        if (lane == 0) { disp[row] = uL - su * wu; conf[row] = 0.0f; }
    }
}

// ---------------------------------------------------------------------------
extern "C" void kernel_launch(void* const* d_in, const int* in_sizes, int n_in,
                              void* d_out, int out_size)
{
    (void)in_sizes; (void)n_in; (void)out_size;

    const float* nodes_L = (const float*)d_in[0];
    const float* nodes_R = (const float*)d_in[1];
    const float* kpts_L  = (const float*)d_in[2];
    const float* kpts_R  = (const float*)d_in[3];
    const float* Wq = (const float*)d_in[4];
    const float* bq = (const float*)d_in[5];
    const float* Wk = (const float*)d_in[6];
    const float* bk = (const float*)d_in[7];
    const float* Wv = (const float*)d_in[8];
    const float* bv = (const float*)d_in[9];
    const float* Wm = (const float*)d_in[10];
    const float* bm = (const float*)d_in[11];

    float* out      = (float*)d_out;
    float* out_feat = out;
    float* out_disp = out_feat + (size_t)KB * KN * KC;
    float* out_conf = out_disp + (size_t)KB * KN;
    float* out_attn = out_conf + (size_t)KB * KN;

    float *pQ, *pK, *pV, *pMF;
    cudaGetSymbolAddress((void**)&pQ,  g_Q);
    cudaGetSymbolAddress((void**)&pK,  g_K);
    cudaGetSymbolAddress((void**)&pV,  g_V);
    cudaGetSymbolAddress((void**)&pMF, g_MF);

    const int gemm_smem = 4 * ABYTES;   // 73728 bytes
    cudaFuncSetAttribute(gemm_qkv, cudaFuncAttributeMaxDynamicSharedMemorySize,
                         gemm_smem);
    cudaFuncSetAttribute(gemm_out, cudaFuncAttributeMaxDynamicSharedMemorySize,
                         gemm_smem);

    build_bins_kernel<<<KB, 512>>>(kpts_R);

    dim3 qkv_grid(KC / BN, KROWS / BM, 3);   // (2, 128, 3)
    gemm_qkv<<<qkv_grid, 256, gemm_smem>>>(nodes_L, nodes_R,
                                           Wq, bq, Wk, bk, Wv, bv,
                                           pQ, pK, pV);

    attn_sparse_kernel<<<KROWS / 8, 256>>>(kpts_L, kpts_R,
                                           out_attn, out_disp, out_conf);

    dim3 out_grid(KC / BN, KROWS / BM);
    gemm_out<<<out_grid, 256, gemm_smem>>>(pMF, Wm, bm, out_feat);
}

// round 5
// speedup vs baseline: 2.9109x; 2.9109x over previous
#include <cuda_runtime.h>
#include <math.h>

// Problem constants
#define KB 4
#define KN 4096
#define KM 4096
#define KC 256
#define KROWS (KB * KN)
#define NBINS 376
#define CAP 1024

// -------------------- device scratch (allocation-free) ---------------------
__device__ float  g_Q[KB * KN * KC];
__device__ float  g_K[KB * KM * KC];
__device__ float  g_V[KB * KM * KC];
__device__ float  g_MF[KB * KN * KC];
__device__ float2 g_bin_uv[KB * KM];
__device__ int    g_bin_idx[KB * KM];
__device__ int    g_bin_off[KB * (NBINS + 1)];

// ---------------------------------------------------------------------------
// v-bin CSR for kpts_R, one block per batch
// ---------------------------------------------------------------------------
__global__ void build_bins_kernel(const float* __restrict__ kptsR)
{
    const int b   = blockIdx.x;
    const int tid = threadIdx.x;
    __shared__ int cnt[NBINS];
    __shared__ int off[NBINS + 1];
    __shared__ int cur[NBINS];

    for (int i = tid; i < NBINS; i += blockDim.x) cnt[i] = 0;
    __syncthreads();

    const float* kR = kptsR + (size_t)b * KM * 2;
    for (int m = tid; m < KM; m += blockDim.x) {
        int bin = (int)kR[2 * m + 1];
        bin = max(0, min(NBINS - 1, bin));
        atomicAdd(&cnt[bin], 1);
    }
    __syncthreads();

    if (tid == 0) {
        off[0] = 0;
        for (int i = 0; i < NBINS; i++) off[i + 1] = off[i] + cnt[i];
    }
    __syncthreads();

    for (int i = tid; i < NBINS; i += blockDim.x) cur[i] = off[i];
    __syncthreads();

    for (int m = tid; m < KM; m += blockDim.x) {
        const float u = kR[2 * m];
        const float v = kR[2 * m + 1];
        int bin = max(0, min(NBINS - 1, (int)v));
        const int p = atomicAdd(&cur[bin], 1);
        g_bin_uv[(size_t)b * KM + p]  = make_float2(u, v);
        g_bin_idx[(size_t)b * KM + p] = m;
    }

    for (int i = tid; i <= NBINS; i += blockDim.x)
        g_bin_off[b * (NBINS + 1) + i] = off[i];
}

// ---------------------------------------------------------------------------
// Grid-stride float4 memset (zero) for the 268 MB attn_weights buffer.
// ---------------------------------------------------------------------------
__global__ void fill_zero_kernel(float4* __restrict__ p, long long n4)
{
    const float4 z = make_float4(0.f, 0.f, 0.f, 0.f);
    const long long stride = (long long)gridDim.x * blockDim.x;
    for (long long i = (long long)blockIdx.x * blockDim.x + threadIdx.x;
         i < n4; i += stride)
        p[i] = z;
}

// ---------------------------------------------------------------------------
// tf32 tensor-core GEMM (NT + bias), cp.async double-buffered.
// 128x128x32 block tile, 8 warps (2m x 4n), warp tile 64x32.
// ---------------------------------------------------------------------------
#define BM 128
#define BN 128
#define BBK 32
#define KPAD (BBK + 4)
#define NTILES (KC / BBK)      // 8
#define ABYTES (BM * KPAD * 4) // 18432 per buffer

__device__ __forceinline__ unsigned f2tf32(float x)
{
    unsigned u;
    asm("cvt.rna.tf32.f32 %0, %1;" : "=r"(u) : "f"(x));
    return u;
}

__device__ __forceinline__ void cp16(void* smem_dst, const void* gmem_src)
{
    unsigned s = (unsigned)__cvta_generic_to_shared(smem_dst);
    asm volatile("cp.async.cg.shared.global [%0], [%1], 16;"
                 :: "r"(s), "l"(gmem_src));
}

__device__ __forceinline__ void gemm_tf32_body(const float* __restrict__ A,
                                               const float* __restrict__ W,
                                               const float* __restrict__ bias,
                                               float* __restrict__ Cout)
{
    extern __shared__ char sm_raw[];
    float (*As)[BM][KPAD] = reinterpret_cast<float (*)[BM][KPAD]>(sm_raw);
    float (*Bs)[BM][KPAD] = reinterpret_cast<float (*)[BM][KPAD]>(sm_raw + 2 * ABYTES);

    const int row0 = blockIdx.y * BM;
    const int col0 = blockIdx.x * BN;
    const int tid  = threadIdx.x;
    const int warp = tid >> 5;
    const int lane = tid & 31;
    const int grp  = lane >> 2;
    const int tg   = lane & 3;
    const int wm   = (warp & 1) * 64;
    const int wn   = (warp >> 1) * 32;

    int cr[4], ck[4];
#pragma unroll
    for (int j = 0; j < 4; j++) {
        const int e = tid + j * 256;
        cr[j] = e >> 3;
        ck[j] = (e & 7) * 4;
    }

    float acc[4][4][4];
#pragma unroll
    for (int mt = 0; mt < 4; mt++)
#pragma unroll
        for (int nt = 0; nt < 4; nt++)
#pragma unroll
            for (int e = 0; e < 4; e++) acc[mt][nt][e] = 0.0f;

#pragma unroll
    for (int j = 0; j < 4; j++) {
        cp16(&As[0][cr[j]][ck[j]], A + (size_t)(row0 + cr[j]) * KC + ck[j]);
        cp16(&Bs[0][cr[j]][ck[j]], W + (size_t)(col0 + cr[j]) * KC + ck[j]);
    }
    asm volatile("cp.async.commit_group;");

#pragma unroll
    for (int t = 0; t < NTILES; t++) {
        const int buf = t & 1;
        if (t + 1 < NTILES) {
            const int nb = (t + 1) & 1;
            const int k0 = (t + 1) * BBK;
#pragma unroll
            for (int j = 0; j < 4; j++) {
                cp16(&As[nb][cr[j]][ck[j]],
                     A + (size_t)(row0 + cr[j]) * KC + k0 + ck[j]);
                cp16(&Bs[nb][cr[j]][ck[j]],
                     W + (size_t)(col0 + cr[j]) * KC + k0 + ck[j]);
            }
            asm volatile("cp.async.commit_group;");
            asm volatile("cp.async.wait_group 1;");
        } else {
            asm volatile("cp.async.wait_group 0;");
        }
        __syncthreads();

#pragma unroll
        for (int ks = 0; ks < BBK; ks += 8) {
            unsigned a[4][4], b[4][2];
#pragma unroll
            for (int mt = 0; mt < 4; mt++) {
                const int m = wm + mt * 16 + grp;
                a[mt][0] = f2tf32(As[buf][m][ks + tg]);
                a[mt][1] = f2tf32(As[buf][m + 8][ks + tg]);
                a[mt][2] = f2tf32(As[buf][m][ks + tg + 4]);
                a[mt][3] = f2tf32(As[buf][m + 8][ks + tg + 4]);
            }
#pragma unroll
            for (int nt = 0; nt < 4; nt++) {
                const int n = wn + nt * 8 + grp;
                b[nt][0] = f2tf32(Bs[buf][n][ks + tg]);
                b[nt][1] = f2tf32(Bs[buf][n][ks + tg + 4]);
            }
#pragma unroll
            for (int mt = 0; mt < 4; mt++)
#pragma unroll
                for (int nt = 0; nt < 4; nt++)
                    asm volatile(
                        "mma.sync.aligned.m16n8k8.row.col.f32.tf32.tf32.f32 "
                        "{%0,%1,%2,%3}, {%4,%5,%6,%7}, {%8,%9}, {%0,%1,%2,%3};"
                        : "+f"(acc[mt][nt][0]), "+f"(acc[mt][nt][1]),
                          "+f"(acc[mt][nt][2]), "+f"(acc[mt][nt][3])
                        : "r"(a[mt][0]), "r"(a[mt][1]),
                          "r"(a[mt][2]), "r"(a[mt][3]),
                          "r"(b[nt][0]), "r"(b[nt][1]));
        }
        __syncthreads();
    }

#pragma unroll
    for (int mt = 0; mt < 4; mt++) {
        const int m = row0 + wm + mt * 16 + grp;
#pragma unroll
        for (int nt = 0; nt < 4; nt++) {
            const int n = col0 + wn + nt * 8 + 2 * tg;
            const float2 bv = *reinterpret_cast<const float2*>(bias + n);
            float2 o0, o1;
            o0.x = acc[mt][nt][0] + bv.x;
            o0.y = acc[mt][nt][1] + bv.y;
            o1.x = acc[mt][nt][2] + bv.x;
            o1.y = acc[mt][nt][3] + bv.y;
            *reinterpret_cast<float2*>(Cout + (size_t)m * KC + n)       = o0;
            *reinterpret_cast<float2*>(Cout + (size_t)(m + 8) * KC + n) = o1;
        }
    }
}

__global__ void __launch_bounds__(256)
gemm_qkv(const float* __restrict__ nodes_L, const float* __restrict__ nodes_R,
         const float* __restrict__ Wq, const float* __restrict__ bq,
         const float* __restrict__ Wk, const float* __restrict__ bk,
         const float* __restrict__ Wv, const float* __restrict__ bv,
         float* __restrict__ Q, float* __restrict__ K, float* __restrict__ V)
{
    const int z = blockIdx.z;
    const float* A    = (z == 0) ? nodes_L : nodes_R;
    const float* W    = (z == 0) ? Wq : (z == 1) ? Wk : Wv;
    const float* bias = (z == 0) ? bq : (z == 1) ? bk : bv;
    float*       C    = (z == 0) ? Q  : (z == 1) ? K  : V;
    gemm_tf32_body(A, W, bias, C);
}

__global__ void __launch_bounds__(256)
gemm_out(const float* __restrict__ A, const float* __restrict__ W,
         const float* __restrict__ bias, float* __restrict__ C)
{
    gemm_tf32_body(A, W, bias, C);
}

// ---------------------------------------------------------------------------
// Sparse epipolar attention. ONE BLOCK (128 threads) PER QUERY ROW.
// Zero-fill of attn rows is done by fill_zero_kernel beforehand; here we only
// scatter the ~10 nonzero weights. Softmax over the candidate list is done by
// warp 0 with shfl (no tree reductions). 4 __syncthreads per block.
// ---------------------------------------------------------------------------
__global__ void __launch_bounds__(128)
attn_sparse_kernel(const float* __restrict__ kptsL,
                   const float* __restrict__ kptsR,
                   float* __restrict__ attn,
                   float* __restrict__ disp,
                   float* __restrict__ conf)
{
    __shared__ int   s_idx[CAP];
    __shared__ float s_du[CAP];
    __shared__ float s_sc[CAP];
    __shared__ __align__(16) float s_q[KC];
    __shared__ int   s_cnt;

    const int row = blockIdx.x;
    const int b   = row >> 12;
    const int tid = threadIdx.x;

    if (tid == 0) s_cnt = 0;
    __syncthreads();

    const float uL = kptsL[(size_t)row * 2 + 0];
    const float vL = kptsL[(size_t)row * 2 + 1];

    int lo = max((int)floorf(vL - 3.0f), 0);
    int hi = min((int)floorf(vL + 3.0f), NBINS - 1);
    const int* off   = g_bin_off + b * (NBINS + 1);
    const int  start = off[lo];
    const int  end   = off[hi + 1];

    for (int j = start + tid; j < end; j += 128) {
        const float2 uv = g_bin_uv[(size_t)b * KM + j];
        const float du = uL - uv.x;
        if (fabsf(vL - uv.y) < 3.0f && du > 0.0f && du < 192.0f) {
            const int p = atomicAdd(&s_cnt, 1);
            if (p < CAP) {
                s_idx[p] = g_bin_idx[(size_t)b * KM + j];
                s_du[p]  = du;
            }
        }
    }
    s_q[tid]       = g_Q[(size_t)row * KC + tid];
    s_q[tid + 128] = g_Q[(size_t)row * KC + tid + 128];
    __syncthreads();

    const int cnt = min(s_cnt, CAP);
    float* attn_row = attn + (size_t)row * KM;

    if (cnt > 0) {
        // scores: one warp per candidate, 4 warps rotate
        const int wid = tid >> 5, lane = tid & 31;
        const float* Kb = g_K + (size_t)b * KM * KC;
        const float4* q4 = reinterpret_cast<const float4*>(s_q);
        const float4 qa = q4[lane];
        const float4 qb = q4[lane + 32];
        for (int i = wid; i < cnt; i += 4) {
            const float4* k4 = reinterpret_cast<const float4*>(
                Kb + (size_t)s_idx[i] * KC);
            const float4 ka = __ldg(k4 + lane);
            const float4 kb = __ldg(k4 + lane + 32);
            float sum = qa.x * ka.x + qa.y * ka.y + qa.z * ka.z + qa.w * ka.w
                      + qb.x * kb.x + qb.y * kb.y + qb.z * kb.z + qb.w * kb.w;
#pragma unroll
            for (int o = 16; o > 0; o >>= 1)
                sum += __shfl_xor_sync(0xffffffffu, sum, o);
            if (lane == 0) s_sc[i] = sum * 0.0625f;   // 1/sqrt(256)
        }
        __syncthreads();

        // softmax + disparity: warp 0 only, shfl reductions
        if (tid < 32) {
            float mx = -1e30f;
            for (int i = tid; i < cnt; i += 32) mx = fmaxf(mx, s_sc[i]);
#pragma unroll
            for (int o = 16; o > 0; o >>= 1)
                mx = fmaxf(mx, __shfl_xor_sync(0xffffffffu, mx, o));

            float sm = 0.0f;
            for (int i = tid; i < cnt; i += 32) {
                const float e = expf(s_sc[i] - mx);
                s_sc[i] = e;
                sm += e;
            }
#pragma unroll
            for (int o = 16; o > 0; o >>= 1)
                sm += __shfl_xor_sync(0xffffffffu, sm, o);
            const float inv = 1.0f / sm;

            float dsum = 0.0f;
            for (int i = tid; i < cnt; i += 32) {
                const float w = s_sc[i] * inv;
                s_sc[i] = w;
                dsum += w * s_du[i];
            }
#pragma unroll
            for (int o = 16; o > 0; o >>= 1)
                dsum += __shfl_xor_sync(0xffffffffu, dsum, o);
            if (tid == 0) { disp[row] = dsum; conf[row] = 1.0f; }
        }
        __syncthreads();

        // scatter nonzero weights (buffer pre-zeroed by fill_zero_kernel)
        for (int i = tid; i < cnt; i += 128) attn_row[s_idx[i]] = s_sc[i];

        // matched features: thread owns channels [2*tid, 2*tid+1]
        const float* Vb = g_V + (size_t)b * KM * KC;
        float2 a = make_float2(0.f, 0.f);
        for (int i = 0; i < cnt; i++) {
            const float w = s_sc[i];
            const float2 v = __ldg(reinterpret_cast<const float2*>(
                Vb + (size_t)s_idx[i] * KC) + tid);
            a.x = fmaf(w, v.x, a.x);
            a.y = fmaf(w, v.y, a.y);
        }
        *(reinterpret_cast<float2*>(g_MF + (size_t)row * KC) + tid) = a;
    } else {
        // fully-masked row: uniform 1/M softmax (exact)
        const float wu = 1.0f / (float)KM;
        const float4 w4 = make_float4(wu, wu, wu, wu);
        float4* ar4 = reinterpret_cast<float4*>(attn_row);
        for (int m = tid; m < KM / 4; m += 128) ar4[m] = w4;

        const float* Vb = g_V + (size_t)b * KM * KC;
        float2 a = make_float2(0.f, 0.f);
        for (int m = 0; m < KM; m++) {
            const float2 v = __ldg(reinterpret_cast<const float2*>(
                Vb + (size_t)m * KC) + tid);
            a.x += v.x; a.y += v.y;
        }
        a.x *= wu; a.y *= wu;
        *(reinterpret_cast<float2*>(g_MF + (size_t)row * KC) + tid) = a;

        const float* kR = kptsR + (size_t)b * KM * 2;
        float su = 0.0f;
        for (int m = tid; m < KM; m += 128) su += kR[2 * m];
        s_sc[tid] = su; __syncthreads();
        for (int s = 64; s > 0; s >>= 1) {
            if (tid < s) s_sc[tid] += s_sc[tid + s];
            __syncthreads();
        }
        if (tid == 0) { disp[row] = uL - s_sc[0] * wu; conf[row] = 0.0f; }
    }
}

// ---------------------------------------------------------------------------
extern "C" void kernel_launch(void* const* d_in, const int* in_sizes, int n_in,
                              void* d_out, int out_size)
{
    (void)in_sizes; (void)n_in; (void)out_size;

    const float* nodes_L = (const float*)d_in[0];
    const float* nodes_R = (const float*)d_in[1];
    const float* kpts_L  = (const float*)d_in[2];
    const float* kpts_R  = (const float*)d_in[3];
    const float* Wq = (const float*)d_in[4];
    const float* bq = (const float*)d_in[5];
    const float* Wk = (const float*)d_in[6];
    const float* bk = (const float*)d_in[7];
    const float* Wv = (const float*)d_in[8];
    const float* bv = (const float*)d_in[9];
    const float* Wm = (const float*)d_in[10];
    const float* bm = (const float*)d_in[11];

    float* out      = (float*)d_out;
    float* out_feat = out;
    float* out_disp = out_feat + (size_t)KB * KN * KC;
    float* out_conf = out_disp + (size_t)KB * KN;
    float* out_attn = out_conf + (size_t)KB * KN;

    float *pQ, *pK, *pV, *pMF;
    cudaGetSymbolAddress((void**)&pQ,  g_Q);
    cudaGetSymbolAddress((void**)&pK,  g_K);
    cudaGetSymbolAddress((void**)&pV,  g_V);
    cudaGetSymbolAddress((void**)&pMF, g_MF);

    const int gemm_smem = 4 * ABYTES;   // 73728 bytes
    cudaFuncSetAttribute(gemm_qkv, cudaFuncAttributeMaxDynamicSharedMemorySize,
                         gemm_smem);
    cudaFuncSetAttribute(gemm_out, cudaFuncAttributeMaxDynamicSharedMemorySize,
                         gemm_smem);

    build_bins_kernel<<<KB, 512>>>(kpts_R);

    // zero-fill attn_weights (268 MB) while bins/GEMM results are produced
    const long long n4 = (long long)KB * KN * KM / 4;
    fill_zero_kernel<<<8192, 256>>>(reinterpret_cast<float4*>(out_attn), n4);

    dim3 qkv_grid(KC / BN, KROWS / BM, 3);
    gemm_qkv<<<qkv_grid, 256, gemm_smem>>>(nodes_L, nodes_R,
                                           Wq, bq, Wk, bk, Wv, bv,
                                           pQ, pK, pV);

    attn_sparse_kernel<<<KROWS, 128>>>(kpts_L, kpts_R,
                                       out_attn, out_disp, out_conf);

    dim3 out_grid(KC / BN, KROWS / BM);
    gemm_out<<<out_grid, 256, gemm_smem>>>(pMF, Wm, bm, out_feat);
}

// round 6
// speedup vs baseline: 2.9270x; 1.0055x over previous
#include <cuda_runtime.h>
#include <math.h>

// Problem constants
#define KB 4
#define KN 4096
#define KM 4096
#define KC 256
#define KROWS (KB * KN)
#define NBINS 376
#define CAP 256

// -------------------- device scratch (allocation-free) ---------------------
__device__ float  g_Q[KB * KN * KC];
__device__ float  g_K[KB * KM * KC];
__device__ float  g_V[KB * KM * KC];
__device__ float  g_MF[KB * KN * KC];
__device__ float2 g_bin_uv[KB * KM];
__device__ int    g_bin_idx[KB * KM];
__device__ int    g_bin_off[KB * (NBINS + 1)];

// ---------------------------------------------------------------------------
// v-bin CSR for kpts_R, one block per batch
// ---------------------------------------------------------------------------
__global__ void build_bins_kernel(const float* __restrict__ kptsR)
{
    const int b   = blockIdx.x;
    const int tid = threadIdx.x;
    __shared__ int cnt[NBINS];
    __shared__ int off[NBINS + 1];
    __shared__ int cur[NBINS];

    for (int i = tid; i < NBINS; i += blockDim.x) cnt[i] = 0;
    __syncthreads();

    const float* kR = kptsR + (size_t)b * KM * 2;
    for (int m = tid; m < KM; m += blockDim.x) {
        int bin = (int)kR[2 * m + 1];
        bin = max(0, min(NBINS - 1, bin));
        atomicAdd(&cnt[bin], 1);
    }
    __syncthreads();

    if (tid == 0) {
        off[0] = 0;
        for (int i = 0; i < NBINS; i++) off[i + 1] = off[i] + cnt[i];
    }
    __syncthreads();

    for (int i = tid; i < NBINS; i += blockDim.x) cur[i] = off[i];
    __syncthreads();

    for (int m = tid; m < KM; m += blockDim.x) {
        const float u = kR[2 * m];
        const float v = kR[2 * m + 1];
        int bin = max(0, min(NBINS - 1, (int)v));
        const int p = atomicAdd(&cur[bin], 1);
        g_bin_uv[(size_t)b * KM + p]  = make_float2(u, v);
        g_bin_idx[(size_t)b * KM + p] = m;
    }

    for (int i = tid; i <= NBINS; i += blockDim.x)
        g_bin_off[b * (NBINS + 1) + i] = off[i];
}

// ---------------------------------------------------------------------------
// tf32 tensor-core GEMM (NT + bias), cp.async double-buffered.
// 128x128x32 block tile, 8 warps (2m x 4n), warp tile 64x32.
// ---------------------------------------------------------------------------
#define BM 128
#define BN 128
#define BBK 32
#define KPAD (BBK + 4)
#define NTILES (KC / BBK)      // 8
#define ABYTES (BM * KPAD * 4) // 18432 per buffer

__device__ __forceinline__ unsigned f2tf32(float x)
{
    unsigned u;
    asm("cvt.rna.tf32.f32 %0, %1;" : "=r"(u) : "f"(x));
    return u;
}

__device__ __forceinline__ void cp16(void* smem_dst, const void* gmem_src)
{
    unsigned s = (unsigned)__cvta_generic_to_shared(smem_dst);
    asm volatile("cp.async.cg.shared.global [%0], [%1], 16;"
                 :: "r"(s), "l"(gmem_src));
}

__device__ __forceinline__ void gemm_tf32_body(const float* __restrict__ A,
                                               const float* __restrict__ W,
                                               const float* __restrict__ bias,
                                               float* __restrict__ Cout)
{
    extern __shared__ char sm_raw[];
    float (*As)[BM][KPAD] = reinterpret_cast<float (*)[BM][KPAD]>(sm_raw);
    float (*Bs)[BM][KPAD] = reinterpret_cast<float (*)[BM][KPAD]>(sm_raw + 2 * ABYTES);

    const int row0 = blockIdx.y * BM;
    const int col0 = blockIdx.x * BN;
    const int tid  = threadIdx.x;
    const int warp = tid >> 5;
    const int lane = tid & 31;
    const int grp  = lane >> 2;
    const int tg   = lane & 3;
    const int wm   = (warp & 1) * 64;
    const int wn   = (warp >> 1) * 32;

    int cr[4], ck[4];
#pragma unroll
    for (int j = 0; j < 4; j++) {
        const int e = tid + j * 256;
        cr[j] = e >> 3;
        ck[j] = (e & 7) * 4;
    }

    float acc[4][4][4];
#pragma unroll
    for (int mt = 0; mt < 4; mt++)
#pragma unroll
        for (int nt = 0; nt < 4; nt++)
#pragma unroll
            for (int e = 0; e < 4; e++) acc[mt][nt][e] = 0.0f;

#pragma unroll
    for (int j = 0; j < 4; j++) {
        cp16(&As[0][cr[j]][ck[j]], A + (size_t)(row0 + cr[j]) * KC + ck[j]);
        cp16(&Bs[0][cr[j]][ck[j]], W + (size_t)(col0 + cr[j]) * KC + ck[j]);
    }
    asm volatile("cp.async.commit_group;");

#pragma unroll
    for (int t = 0; t < NTILES; t++) {
        const int buf = t & 1;
        if (t + 1 < NTILES) {
            const int nb = (t + 1) & 1;
            const int k0 = (t + 1) * BBK;
#pragma unroll
            for (int j = 0; j < 4; j++) {
                cp16(&As[nb][cr[j]][ck[j]],
                     A + (size_t)(row0 + cr[j]) * KC + k0 + ck[j]);
                cp16(&Bs[nb][cr[j]][ck[j]],
                     W + (size_t)(col0 + cr[j]) * KC + k0 + ck[j]);
            }
            asm volatile("cp.async.commit_group;");
            asm volatile("cp.async.wait_group 1;");
        } else {
            asm volatile("cp.async.wait_group 0;");
        }
        __syncthreads();

#pragma unroll
        for (int ks = 0; ks < BBK; ks += 8) {
            unsigned a[4][4], b[4][2];
#pragma unroll
            for (int mt = 0; mt < 4; mt++) {
                const int m = wm + mt * 16 + grp;
                a[mt][0] = f2tf32(As[buf][m][ks + tg]);
                a[mt][1] = f2tf32(As[buf][m + 8][ks + tg]);
                a[mt][2] = f2tf32(As[buf][m][ks + tg + 4]);
                a[mt][3] = f2tf32(As[buf][m + 8][ks + tg + 4]);
            }
#pragma unroll
            for (int nt = 0; nt < 4; nt++) {
                const int n = wn + nt * 8 + grp;
                b[nt][0] = f2tf32(Bs[buf][n][ks + tg]);
                b[nt][1] = f2tf32(Bs[buf][n][ks + tg + 4]);
            }
#pragma unroll
            for (int mt = 0; mt < 4; mt++)
#pragma unroll
                for (int nt = 0; nt < 4; nt++)
                    asm volatile(
                        "mma.sync.aligned.m16n8k8.row.col.f32.tf32.tf32.f32 "
                        "{%0,%1,%2,%3}, {%4,%5,%6,%7}, {%8,%9}, {%0,%1,%2,%3};"
                        : "+f"(acc[mt][nt][0]), "+f"(acc[mt][nt][1]),
                          "+f"(acc[mt][nt][2]), "+f"(acc[mt][nt][3])
                        : "r"(a[mt][0]), "r"(a[mt][1]),
                          "r"(a[mt][2]), "r"(a[mt][3]),
                          "r"(b[nt][0]), "r"(b[nt][1]));
        }
        __syncthreads();
    }

#pragma unroll
    for (int mt = 0; mt < 4; mt++) {
        const int m = row0 + wm + mt * 16 + grp;
#pragma unroll
        for (int nt = 0; nt < 4; nt++) {
            const int n = col0 + wn + nt * 8 + 2 * tg;
            const float2 bv = *reinterpret_cast<const float2*>(bias + n);
            float2 o0, o1;
            o0.x = acc[mt][nt][0] + bv.x;
            o0.y = acc[mt][nt][1] + bv.y;
            o1.x = acc[mt][nt][2] + bv.x;
            o1.y = acc[mt][nt][3] + bv.y;
            *reinterpret_cast<float2*>(Cout + (size_t)m * KC + n)       = o0;
            *reinterpret_cast<float2*>(Cout + (size_t)(m + 8) * KC + n) = o1;
        }
    }
}

__global__ void __launch_bounds__(256)
gemm_qkv(const float* __restrict__ nodes_L, const float* __restrict__ nodes_R,
         const float* __restrict__ Wq, const float* __restrict__ bq,
         const float* __restrict__ Wk, const float* __restrict__ bk,
         const float* __restrict__ Wv, const float* __restrict__ bv,
         float* __restrict__ Q, float* __restrict__ K, float* __restrict__ V)
{
    const int z = blockIdx.z;
    const float* A    = (z == 0) ? nodes_L : nodes_R;
    const float* W    = (z == 0) ? Wq : (z == 1) ? Wk : Wv;
    const float* bias = (z == 0) ? bq : (z == 1) ? bk : bv;
    float*       C    = (z == 0) ? Q  : (z == 1) ? K  : V;
    gemm_tf32_body(A, W, bias, C);
}

__global__ void __launch_bounds__(256)
gemm_out(const float* __restrict__ A, const float* __restrict__ W,
         const float* __restrict__ bias, float* __restrict__ C)
{
    gemm_tf32_body(A, W, bias, C);
}

// ---------------------------------------------------------------------------
// Sparse epipolar attention. ONE BLOCK (128 threads) PER QUERY ROW.
// Small smem footprint (CAP=256) for high occupancy; zero-fill of the attn
// row is done in-block with streaming stores (overlaps gather latency);
// score and MF gather loops are unrolled for memory-level parallelism.
// ---------------------------------------------------------------------------
__global__ void __launch_bounds__(128, 12)
attn_sparse_kernel(const float* __restrict__ kptsL,
                   const float* __restrict__ kptsR,
                   float* __restrict__ attn,
                   float* __restrict__ disp,
                   float* __restrict__ conf)
{
    __shared__ int   s_idx[CAP];
    __shared__ float s_du[CAP];
    __shared__ float s_sc[CAP];
    __shared__ __align__(16) float s_q[KC];
    __shared__ int   s_cnt;

    const int row = blockIdx.x;
    const int b   = row >> 12;
    const int tid = threadIdx.x;

    if (tid == 0) s_cnt = 0;
    __syncthreads();

    const float uL = kptsL[(size_t)row * 2 + 0];
    const float vL = kptsL[(size_t)row * 2 + 1];

    int lo = max((int)floorf(vL - 3.0f), 0);
    int hi = min((int)floorf(vL + 3.0f), NBINS - 1);
    const int* off   = g_bin_off + b * (NBINS + 1);
    const int  start = off[lo];
    const int  end   = off[hi + 1];

    for (int j = start + tid; j < end; j += 128) {
        const float2 uv = g_bin_uv[(size_t)b * KM + j];
        const float du = uL - uv.x;
        if (fabsf(vL - uv.y) < 3.0f && du > 0.0f && du < 192.0f) {
            const int p = atomicAdd(&s_cnt, 1);
            if (p < CAP) {
                s_idx[p] = g_bin_idx[(size_t)b * KM + j];
                s_du[p]  = du;
            }
        }
    }
    s_q[tid]       = g_Q[(size_t)row * KC + tid];
    s_q[tid + 128] = g_Q[(size_t)row * KC + tid + 128];
    __syncthreads();

    const int cnt = min(s_cnt, CAP);
    float* attn_row = attn + (size_t)row * KM;
    float4* ar4 = reinterpret_cast<float4*>(attn_row);

    if (cnt > 0) {
        // ---- zero-fill the 16KB attn row with streaming stores (overlaps
        //      the gathers below across warps) ----
        const float4 z4 = make_float4(0.f, 0.f, 0.f, 0.f);
#pragma unroll
        for (int t = 0; t < KM / 4 / 128; t++) __stcs(&ar4[tid + 128 * t], z4);

        // ---- scores: 4 warps, 2 candidates in flight per warp ----
        const int wid = tid >> 5, lane = tid & 31;
        const float* Kb = g_K + (size_t)b * KM * KC;
        const float4* q4 = reinterpret_cast<const float4*>(s_q);
        const float4 qa = q4[lane];
        const float4 qb = q4[lane + 32];
        for (int i = wid * 2; i < cnt; i += 8) {
            const float4* k4a = reinterpret_cast<const float4*>(
                Kb + (size_t)s_idx[i] * KC);
            const bool has2 = (i + 1 < cnt);
            const float4* k4b = reinterpret_cast<const float4*>(
                Kb + (size_t)s_idx[has2 ? i + 1 : i] * KC);
            // issue all 4 gathers before reducing
            const float4 ka0 = __ldg(k4a + lane);
            const float4 ka1 = __ldg(k4a + lane + 32);
            const float4 kb0 = __ldg(k4b + lane);
            const float4 kb1 = __ldg(k4b + lane + 32);
            float s0 = qa.x * ka0.x + qa.y * ka0.y + qa.z * ka0.z + qa.w * ka0.w
                     + qb.x * ka1.x + qb.y * ka1.y + qb.z * ka1.z + qb.w * ka1.w;
            float s1 = qa.x * kb0.x + qa.y * kb0.y + qa.z * kb0.z + qa.w * kb0.w
                     + qb.x * kb1.x + qb.y * kb1.y + qb.z * kb1.z + qb.w * kb1.w;
#pragma unroll
            for (int o = 16; o > 0; o >>= 1) {
                s0 += __shfl_xor_sync(0xffffffffu, s0, o);
                s1 += __shfl_xor_sync(0xffffffffu, s1, o);
            }
            if (lane == 0) {
                s_sc[i] = s0 * 0.0625f;                 // 1/sqrt(256)
                if (has2) s_sc[i + 1] = s1 * 0.0625f;
            }
        }
        __syncthreads();

        // ---- softmax + disparity: warp 0, shfl reductions ----
        if (tid < 32) {
            float mx = -1e30f;
            for (int i = tid; i < cnt; i += 32) mx = fmaxf(mx, s_sc[i]);
#pragma unroll
            for (int o = 16; o > 0; o >>= 1)
                mx = fmaxf(mx, __shfl_xor_sync(0xffffffffu, mx, o));

            float sm = 0.0f;
            for (int i = tid; i < cnt; i += 32) {
                const float e = expf(s_sc[i] - mx);
                s_sc[i] = e;
                sm += e;
            }
#pragma unroll
            for (int o = 16; o > 0; o >>= 1)
                sm += __shfl_xor_sync(0xffffffffu, sm, o);
            const float inv = 1.0f / sm;

            float dsum = 0.0f;
            for (int i = tid; i < cnt; i += 32) {
                const float w = s_sc[i] * inv;
                s_sc[i] = w;
                dsum += w * s_du[i];
            }
#pragma unroll
            for (int o = 16; o > 0; o >>= 1)
                dsum += __shfl_xor_sync(0xffffffffu, dsum, o);
            if (tid == 0) { disp[row] = dsum; conf[row] = 1.0f; }
        }
        __syncthreads();   // weights final AND zero-fill complete

        // ---- scatter nonzero weights over the zeroed row ----
        for (int i = tid; i < cnt; i += 128) attn_row[s_idx[i]] = s_sc[i];

        // ---- matched features: thread owns 2 channels; 4 gathers in flight
        const float2* Vb2 = reinterpret_cast<const float2*>(
            g_V + (size_t)b * KM * KC);
        float2 a0 = make_float2(0.f, 0.f), a1 = a0, a2 = a0, a3 = a0;
        int i = 0;
        for (; i + 4 <= cnt; i += 4) {
            const float w0 = s_sc[i],     w1 = s_sc[i + 1];
            const float w2 = s_sc[i + 2], w3 = s_sc[i + 3];
            const float2 v0 = __ldg(Vb2 + (size_t)s_idx[i]     * (KC / 2) + tid);
            const float2 v1 = __ldg(Vb2 + (size_t)s_idx[i + 1] * (KC / 2) + tid);
            const float2 v2 = __ldg(Vb2 + (size_t)s_idx[i + 2] * (KC / 2) + tid);
            const float2 v3 = __ldg(Vb2 + (size_t)s_idx[i + 3] * (KC / 2) + tid);
            a0.x = fmaf(w0, v0.x, a0.x); a0.y = fmaf(w0, v0.y, a0.y);
            a1.x = fmaf(w1, v1.x, a1.x); a1.y = fmaf(w1, v1.y, a1.y);
            a2.x = fmaf(w2, v2.x, a2.x); a2.y = fmaf(w2, v2.y, a2.y);
            a3.x = fmaf(w3, v3.x, a3.x); a3.y = fmaf(w3, v3.y, a3.y);
        }
        for (; i < cnt; i++) {
            const float w = s_sc[i];
            const float2 v = __ldg(Vb2 + (size_t)s_idx[i] * (KC / 2) + tid);
            a0.x = fmaf(w, v.x, a0.x); a0.y = fmaf(w, v.y, a0.y);
        }
        float2 a;
        a.x = (a0.x + a1.x) + (a2.x + a3.x);
        a.y = (a0.y + a1.y) + (a2.y + a3.y);
        *(reinterpret_cast<float2*>(g_MF + (size_t)row * KC) + tid) = a;
    } else {
        // fully-masked row: uniform 1/M softmax (exact)
        const float wu = 1.0f / (float)KM;
        const float4 w4 = make_float4(wu, wu, wu, wu);
#pragma unroll
        for (int t = 0; t < KM / 4 / 128; t++) __stcs(&ar4[tid + 128 * t], w4);

        const float2* Vb2 = reinterpret_cast<const float2*>(
            g_V + (size_t)b * KM * KC);
        float2 a0 = make_float2(0.f, 0.f), a1 = a0, a2 = a0, a3 = a0;
        for (int m = 0; m < KM; m += 4) {
            const float2 v0 = __ldg(Vb2 + (size_t)m       * (KC / 2) + tid);
            const float2 v1 = __ldg(Vb2 + (size_t)(m + 1) * (KC / 2) + tid);
            const float2 v2 = __ldg(Vb2 + (size_t)(m + 2) * (KC / 2) + tid);
            const float2 v3 = __ldg(Vb2 + (size_t)(m + 3) * (KC / 2) + tid);
            a0.x += v0.x; a0.y += v0.y;
            a1.x += v1.x; a1.y += v1.y;
            a2.x += v2.x; a2.y += v2.y;
            a3.x += v3.x; a3.y += v3.y;
        }
        float2 a;
        a.x = ((a0.x + a1.x) + (a2.x + a3.x)) * wu;
        a.y = ((a0.y + a1.y) + (a2.y + a3.y)) * wu;
        *(reinterpret_cast<float2*>(g_MF + (size_t)row * KC) + tid) = a;

        const float* kR = kptsR + (size_t)b * KM * 2;
        float su = 0.0f;
        for (int m = tid; m < KM; m += 128) su += kR[2 * m];
        s_sc[tid & 127] = su; __syncthreads();
        if (tid < 32) {
            float t = s_sc[tid] + s_sc[tid + 32] + s_sc[tid + 64] + s_sc[tid + 96];
#pragma unroll
            for (int o = 16; o > 0; o >>= 1)
                t += __shfl_xor_sync(0xffffffffu, t, o);
            if (tid == 0) { disp[row] = uL - t * wu; conf[row] = 0.0f; }
        }
    }
}

// ---------------------------------------------------------------------------
extern "C" void kernel_launch(void* const* d_in, const int* in_sizes, int n_in,
                              void* d_out, int out_size)
{
    (void)in_sizes; (void)n_in; (void)out_size;

    const float* nodes_L = (const float*)d_in[0];
    const float* nodes_R = (const float*)d_in[1];
    const float* kpts_L  = (const float*)d_in[2];
    const float* kpts_R  = (const float*)d_in[3];
    const float* Wq = (const float*)d_in[4];
    const float* bq = (const float*)d_in[5];
    const float* Wk = (const float*)d_in[6];
    const float* bk = (const float*)d_in[7];
    const float* Wv = (const float*)d_in[8];
    const float* bv = (const float*)d_in[9];
    const float* Wm = (const float*)d_in[10];
    const float* bm = (const float*)d_in[11];

    float* out      = (float*)d_out;
    float* out_feat = out;
    float* out_disp = out_feat + (size_t)KB * KN * KC;
    float* out_conf = out_disp + (size_t)KB * KN;
    float* out_attn = out_conf + (size_t)KB * KN;

    float *pQ, *pK, *pV, *pMF;
    cudaGetSymbolAddress((void**)&pQ,  g_Q);
    cudaGetSymbolAddress((void**)&pK,  g_K);
    cudaGetSymbolAddress((void**)&pV,  g_V);
    cudaGetSymbolAddress((void**)&pMF, g_MF);

    const int gemm_smem = 4 * ABYTES;   // 73728 bytes
    cudaFuncSetAttribute(gemm_qkv, cudaFuncAttributeMaxDynamicSharedMemorySize,
                         gemm_smem);
    cudaFuncSetAttribute(gemm_out, cudaFuncAttributeMaxDynamicSharedMemorySize,
                         gemm_smem);

    build_bins_kernel<<<KB, 512>>>(kpts_R);

    dim3 qkv_grid(KC / BN, KROWS / BM, 3);
    gemm_qkv<<<qkv_grid, 256, gemm_smem>>>(nodes_L, nodes_R,
                                           Wq, bq, Wk, bk, Wv, bv,
                                           pQ, pK, pV);

    attn_sparse_kernel<<<KROWS, 128>>>(kpts_L, kpts_R,
                                       out_attn, out_disp, out_conf);

    dim3 out_grid(KC / BN, KROWS / BM);
    gemm_out<<<out_grid, 256, gemm_smem>>>(pMF, Wm, bm, out_feat);
}

// round 7
// speedup vs baseline: 2.9331x; 1.0021x over previous
#include <cuda_runtime.h>
#include <math.h>

// Problem constants
#define KB 4
#define KN 4096
#define KM 4096
#define KC 256
#define KROWS (KB * KN)
#define NBINS 376
#define CAP 256

// -------------------- device scratch (allocation-free) ---------------------
__device__ float  g_Q[KB * KN * KC];
__device__ float  g_K[KB * KM * KC];
__device__ float  g_V[KB * KM * KC];
__device__ float  g_MF[KB * KN * KC];
__device__ float2 g_bin_uv[KB * KM];
__device__ int    g_bin_idx[KB * KM];
__device__ int    g_bin_off[KB * (NBINS + 1)];

// ---------------------------------------------------------------------------
// v-bin CSR for kpts_R, one block per batch
// ---------------------------------------------------------------------------
__global__ void build_bins_kernel(const float* __restrict__ kptsR)
{
    const int b   = blockIdx.x;
    const int tid = threadIdx.x;
    __shared__ int cnt[NBINS];
    __shared__ int off[NBINS + 1];
    __shared__ int cur[NBINS];

    for (int i = tid; i < NBINS; i += blockDim.x) cnt[i] = 0;
    __syncthreads();

    const float* kR = kptsR + (size_t)b * KM * 2;
    for (int m = tid; m < KM; m += blockDim.x) {
        int bin = (int)kR[2 * m + 1];
        bin = max(0, min(NBINS - 1, bin));
        atomicAdd(&cnt[bin], 1);
    }
    __syncthreads();

    if (tid == 0) {
        off[0] = 0;
        for (int i = 0; i < NBINS; i++) off[i + 1] = off[i] + cnt[i];
    }
    __syncthreads();

    for (int i = tid; i < NBINS; i += blockDim.x) cur[i] = off[i];
    __syncthreads();

    for (int m = tid; m < KM; m += blockDim.x) {
        const float u = kR[2 * m];
        const float v = kR[2 * m + 1];
        int bin = max(0, min(NBINS - 1, (int)v));
        const int p = atomicAdd(&cur[bin], 1);
        g_bin_uv[(size_t)b * KM + p]  = make_float2(u, v);
        g_bin_idx[(size_t)b * KM + p] = m;
    }

    for (int i = tid; i <= NBINS; i += blockDim.x)
        g_bin_off[b * (NBINS + 1) + i] = off[i];
}

// ---------------------------------------------------------------------------
// tf32 tensor-core GEMM (NT + bias), cp.async double-buffered.
// 128x128x32 block tile, 8 warps (2m x 4n), warp tile 64x32.
// ---------------------------------------------------------------------------
#define BM 128
#define BN 128
#define BBK 32
#define KPAD (BBK + 4)
#define NTILES (KC / BBK)      // 8
#define ABYTES (BM * KPAD * 4) // 18432 per buffer

__device__ __forceinline__ unsigned f2tf32(float x)
{
    unsigned u;
    asm("cvt.rna.tf32.f32 %0, %1;" : "=r"(u) : "f"(x));
    return u;
}

__device__ __forceinline__ void cp16(void* smem_dst, const void* gmem_src)
{
    unsigned s = (unsigned)__cvta_generic_to_shared(smem_dst);
    asm volatile("cp.async.cg.shared.global [%0], [%1], 16;"
                 :: "r"(s), "l"(gmem_src));
}

__device__ __forceinline__ void gemm_tf32_body(const float* __restrict__ A,
                                               const float* __restrict__ W,
                                               const float* __restrict__ bias,
                                               float* __restrict__ Cout)
{
    extern __shared__ char sm_raw[];
    float (*As)[BM][KPAD] = reinterpret_cast<float (*)[BM][KPAD]>(sm_raw);
    float (*Bs)[BM][KPAD] = reinterpret_cast<float (*)[BM][KPAD]>(sm_raw + 2 * ABYTES);

    const int row0 = blockIdx.y * BM;
    const int col0 = blockIdx.x * BN;
    const int tid  = threadIdx.x;
    const int warp = tid >> 5;
    const int lane = tid & 31;
    const int grp  = lane >> 2;
    const int tg   = lane & 3;
    const int wm   = (warp & 1) * 64;
    const int wn   = (warp >> 1) * 32;

    int cr[4], ck[4];
#pragma unroll
    for (int j = 0; j < 4; j++) {
        const int e = tid + j * 256;
        cr[j] = e >> 3;
        ck[j] = (e & 7) * 4;
    }

    float acc[4][4][4];
#pragma unroll
    for (int mt = 0; mt < 4; mt++)
#pragma unroll
        for (int nt = 0; nt < 4; nt++)
#pragma unroll
            for (int e = 0; e < 4; e++) acc[mt][nt][e] = 0.0f;

#pragma unroll
    for (int j = 0; j < 4; j++) {
        cp16(&As[0][cr[j]][ck[j]], A + (size_t)(row0 + cr[j]) * KC + ck[j]);
        cp16(&Bs[0][cr[j]][ck[j]], W + (size_t)(col0 + cr[j]) * KC + ck[j]);
    }
    asm volatile("cp.async.commit_group;");

#pragma unroll
    for (int t = 0; t < NTILES; t++) {
        const int buf = t & 1;
        if (t + 1 < NTILES) {
            const int nb = (t + 1) & 1;
            const int k0 = (t + 1) * BBK;
#pragma unroll
            for (int j = 0; j < 4; j++) {
                cp16(&As[nb][cr[j]][ck[j]],
                     A + (size_t)(row0 + cr[j]) * KC + k0 + ck[j]);
                cp16(&Bs[nb][cr[j]][ck[j]],
                     W + (size_t)(col0 + cr[j]) * KC + k0 + ck[j]);
            }
            asm volatile("cp.async.commit_group;");
            asm volatile("cp.async.wait_group 1;");
        } else {
            asm volatile("cp.async.wait_group 0;");
        }
        __syncthreads();

#pragma unroll
        for (int ks = 0; ks < BBK; ks += 8) {
            unsigned a[4][4], b[4][2];
#pragma unroll
            for (int mt = 0; mt < 4; mt++) {
                const int m = wm + mt * 16 + grp;
                a[mt][0] = f2tf32(As[buf][m][ks + tg]);
                a[mt][1] = f2tf32(As[buf][m + 8][ks + tg]);
                a[mt][2] = f2tf32(As[buf][m][ks + tg + 4]);
                a[mt][3] = f2tf32(As[buf][m + 8][ks + tg + 4]);
            }
#pragma unroll
            for (int nt = 0; nt < 4; nt++) {
                const int n = wn + nt * 8 + grp;
                b[nt][0] = f2tf32(Bs[buf][n][ks + tg]);
                b[nt][1] = f2tf32(Bs[buf][n][ks + tg + 4]);
            }
#pragma unroll
            for (int mt = 0; mt < 4; mt++)
#pragma unroll
                for (int nt = 0; nt < 4; nt++)
                    asm volatile(
                        "mma.sync.aligned.m16n8k8.row.col.f32.tf32.tf32.f32 "
                        "{%0,%1,%2,%3}, {%4,%5,%6,%7}, {%8,%9}, {%0,%1,%2,%3};"
                        : "+f"(acc[mt][nt][0]), "+f"(acc[mt][nt][1]),
                          "+f"(acc[mt][nt][2]), "+f"(acc[mt][nt][3])
                        : "r"(a[mt][0]), "r"(a[mt][1]),
                          "r"(a[mt][2]), "r"(a[mt][3]),
                          "r"(b[nt][0]), "r"(b[nt][1]));
        }
        __syncthreads();
    }

#pragma unroll
    for (int mt = 0; mt < 4; mt++) {
        const int m = row0 + wm + mt * 16 + grp;
#pragma unroll
        for (int nt = 0; nt < 4; nt++) {
            const int n = col0 + wn + nt * 8 + 2 * tg;
            const float2 bv = *reinterpret_cast<const float2*>(bias + n);
            float2 o0, o1;
            o0.x = acc[mt][nt][0] + bv.x;
            o0.y = acc[mt][nt][1] + bv.y;
            o1.x = acc[mt][nt][2] + bv.x;
            o1.y = acc[mt][nt][3] + bv.y;
            *reinterpret_cast<float2*>(Cout + (size_t)m * KC + n)       = o0;
            *reinterpret_cast<float2*>(Cout + (size_t)(m + 8) * KC + n) = o1;
        }
    }
}

__global__ void __launch_bounds__(256)
gemm_qkv(const float* __restrict__ nodes_L, const float* __restrict__ nodes_R,
         const float* __restrict__ Wq, const float* __restrict__ bq,
         const float* __restrict__ Wk, const float* __restrict__ bk,
         const float* __restrict__ Wv, const float* __restrict__ bv,
         float* __restrict__ Q, float* __restrict__ K, float* __restrict__ V)
{
    const int z = blockIdx.z;
    const float* A    = (z == 0) ? nodes_L : nodes_R;
    const float* W    = (z == 0) ? Wq : (z == 1) ? Wk : Wv;
    const float* bias = (z == 0) ? bq : (z == 1) ? bk : bv;
    float*       C    = (z == 0) ? Q  : (z == 1) ? K  : V;
    gemm_tf32_body(A, W, bias, C);
}

__global__ void __launch_bounds__(256)
gemm_out(const float* __restrict__ A, const float* __restrict__ W,
         const float* __restrict__ bias, float* __restrict__ C)
{
    gemm_tf32_body(A, W, bias, C);
}

// ---------------------------------------------------------------------------
// Sparse epipolar attention. ONE BLOCK (128 threads) PER QUERY ROW.
// Small smem footprint (CAP=256) for high occupancy; zero-fill of the attn
// row is done in-block with streaming stores (overlaps gather latency);
// score and MF gather loops are unrolled for memory-level parallelism.
// ---------------------------------------------------------------------------
__global__ void __launch_bounds__(128, 12)
attn_sparse_kernel(const float* __restrict__ kptsL,
                   const float* __restrict__ kptsR,
                   float* __restrict__ attn,
                   float* __restrict__ disp,
                   float* __restrict__ conf)
{
    __shared__ int   s_idx[CAP];
    __shared__ float s_du[CAP];
    __shared__ float s_sc[CAP];
    __shared__ __align__(16) float s_q[KC];
    __shared__ int   s_cnt;

    const int row = blockIdx.x;
    const int b   = row >> 12;
    const int tid = threadIdx.x;

    if (tid == 0) s_cnt = 0;
    __syncthreads();

    const float uL = kptsL[(size_t)row * 2 + 0];
    const float vL = kptsL[(size_t)row * 2 + 1];

    int lo = max((int)floorf(vL - 3.0f), 0);
    int hi = min((int)floorf(vL + 3.0f), NBINS - 1);
    const int* off   = g_bin_off + b * (NBINS + 1);
    const int  start = off[lo];
    const int  end   = off[hi + 1];

    for (int j = start + tid; j < end; j += 128) {
        const float2 uv = g_bin_uv[(size_t)b * KM + j];
        const float du = uL - uv.x;
        if (fabsf(vL - uv.y) < 3.0f && du > 0.0f && du < 192.0f) {
            const int p = atomicAdd(&s_cnt, 1);
            if (p < CAP) {
                s_idx[p] = g_bin_idx[(size_t)b * KM + j];
                s_du[p]  = du;
            }
        }
    }
    s_q[tid]       = g_Q[(size_t)row * KC + tid];
    s_q[tid + 128] = g_Q[(size_t)row * KC + tid + 128];
    __syncthreads();

    const int cnt = min(s_cnt, CAP);
    float* attn_row = attn + (size_t)row * KM;
    float4* ar4 = reinterpret_cast<float4*>(attn_row);

    if (cnt > 0) {
        // ---- zero-fill the 16KB attn row with streaming stores (overlaps
        //      the gathers below across warps) ----
        const float4 z4 = make_float4(0.f, 0.f, 0.f, 0.f);
#pragma unroll
        for (int t = 0; t < KM / 4 / 128; t++) __stcs(&ar4[tid + 128 * t], z4);

        // ---- scores: 4 warps, 2 candidates in flight per warp ----
        const int wid = tid >> 5, lane = tid & 31;
        const float* Kb = g_K + (size_t)b * KM * KC;
        const float4* q4 = reinterpret_cast<const float4*>(s_q);
        const float4 qa = q4[lane];
        const float4 qb = q4[lane + 32];
        for (int i = wid * 2; i < cnt; i += 8) {
            const float4* k4a = reinterpret_cast<const float4*>(
                Kb + (size_t)s_idx[i] * KC);
            const bool has2 = (i + 1 < cnt);
            const float4* k4b = reinterpret_cast<const float4*>(
                Kb + (size_t)s_idx[has2 ? i + 1 : i] * KC);
            // issue all 4 gathers before reducing
            const float4 ka0 = __ldg(k4a + lane);
            const float4 ka1 = __ldg(k4a + lane + 32);
            const float4 kb0 = __ldg(k4b + lane);
            const float4 kb1 = __ldg(k4b + lane + 32);
            float s0 = qa.x * ka0.x + qa.y * ka0.y + qa.z * ka0.z + qa.w * ka0.w
                     + qb.x * ka1.x + qb.y * ka1.y + qb.z * ka1.z + qb.w * ka1.w;
            float s1 = qa.x * kb0.x + qa.y * kb0.y + qa.z * kb0.z + qa.w * kb0.w
                     + qb.x * kb1.x + qb.y * kb1.y + qb.z * kb1.z + qb.w * kb1.w;
#pragma unroll
            for (int o = 16; o > 0; o >>= 1) {
                s0 += __shfl_xor_sync(0xffffffffu, s0, o);
                s1 += __shfl_xor_sync(0xffffffffu, s1, o);
            }
            if (lane == 0) {
                s_sc[i] = s0 * 0.0625f;                 // 1/sqrt(256)
                if (has2) s_sc[i + 1] = s1 * 0.0625f;
            }
        }
        __syncthreads();

        // ---- softmax + disparity: warp 0, shfl reductions ----
        if (tid < 32) {
            float mx = -1e30f;
            for (int i = tid; i < cnt; i += 32) mx = fmaxf(mx, s_sc[i]);
#pragma unroll
            for (int o = 16; o > 0; o >>= 1)
                mx = fmaxf(mx, __shfl_xor_sync(0xffffffffu, mx, o));

            float sm = 0.0f;
            for (int i = tid; i < cnt; i += 32) {
                const float e = expf(s_sc[i] - mx);
                s_sc[i] = e;
                sm += e;
            }
#pragma unroll
            for (int o = 16; o > 0; o >>= 1)
                sm += __shfl_xor_sync(0xffffffffu, sm, o);
            const float inv = 1.0f / sm;

            float dsum = 0.0f;
            for (int i = tid; i < cnt; i += 32) {
                const float w = s_sc[i] * inv;
                s_sc[i] = w;
                dsum += w * s_du[i];
            }
#pragma unroll
            for (int o = 16; o > 0; o >>= 1)
                dsum += __shfl_xor_sync(0xffffffffu, dsum, o);
            if (tid == 0) { disp[row] = dsum; conf[row] = 1.0f; }
        }
        __syncthreads();   // weights final AND zero-fill complete

        // ---- scatter nonzero weights over the zeroed row ----
        for (int i = tid; i < cnt; i += 128) attn_row[s_idx[i]] = s_sc[i];

        // ---- matched features: thread owns 2 channels; 4 gathers in flight
        const float2* Vb2 = reinterpret_cast<const float2*>(
            g_V + (size_t)b * KM * KC);
        float2 a0 = make_float2(0.f, 0.f), a1 = a0, a2 = a0, a3 = a0;
        int i = 0;
        for (; i + 4 <= cnt; i += 4) {
            const float w0 = s_sc[i],     w1 = s_sc[i + 1];
            const float w2 = s_sc[i + 2], w3 = s_sc[i + 3];
            const float2 v0 = __ldg(Vb2 + (size_t)s_idx[i]     * (KC / 2) + tid);
            const float2 v1 = __ldg(Vb2 + (size_t)s_idx[i + 1] * (KC / 2) + tid);
            const float2 v2 = __ldg(Vb2 + (size_t)s_idx[i + 2] * (KC / 2) + tid);
            const float2 v3 = __ldg(Vb2 + (size_t)s_idx[i + 3] * (KC / 2) + tid);
            a0.x = fmaf(w0, v0.x, a0.x); a0.y = fmaf(w0, v0.y, a0.y);
            a1.x = fmaf(w1, v1.x, a1.x); a1.y = fmaf(w1, v1.y, a1.y);
            a2.x = fmaf(w2, v2.x, a2.x); a2.y = fmaf(w2, v2.y, a2.y);
            a3.x = fmaf(w3, v3.x, a3.x); a3.y = fmaf(w3, v3.y, a3.y);
        }
        for (; i < cnt; i++) {
            const float w = s_sc[i];
            const float2 v = __ldg(Vb2 + (size_t)s_idx[i] * (KC / 2) + tid);
            a0.x = fmaf(w, v.x, a0.x); a0.y = fmaf(w, v.y, a0.y);
        }
        float2 a;
        a.x = (a0.x + a1.x) + (a2.x + a3.x);
        a.y = (a0.y + a1.y) + (a2.y + a3.y);
        *(reinterpret_cast<float2*>(g_MF + (size_t)row * KC) + tid) = a;
    } else {
        // fully-masked row: uniform 1/M softmax (exact)
        const float wu = 1.0f / (float)KM;
        const float4 w4 = make_float4(wu, wu, wu, wu);
#pragma unroll
        for (int t = 0; t < KM / 4 / 128; t++) __stcs(&ar4[tid + 128 * t], w4);

        const float2* Vb2 = reinterpret_cast<const float2*>(
            g_V + (size_t)b * KM * KC);
        float2 a0 = make_float2(0.f, 0.f), a1 = a0, a2 = a0, a3 = a0;
        for (int m = 0; m < KM; m += 4) {
            const float2 v0 = __ldg(Vb2 + (size_t)m       * (KC / 2) + tid);
            const float2 v1 = __ldg(Vb2 + (size_t)(m + 1) * (KC / 2) + tid);
            const float2 v2 = __ldg(Vb2 + (size_t)(m + 2) * (KC / 2) + tid);
            const float2 v3 = __ldg(Vb2 + (size_t)(m + 3) * (KC / 2) + tid);
            a0.x += v0.x; a0.y += v0.y;
            a1.x += v1.x; a1.y += v1.y;
            a2.x += v2.x; a2.y += v2.y;
            a3.x += v3.x; a3.y += v3.y;
        }
        float2 a;
        a.x = ((a0.x + a1.x) + (a2.x + a3.x)) * wu;
        a.y = ((a0.y + a1.y) + (a2.y + a3.y)) * wu;
        *(reinterpret_cast<float2*>(g_MF + (size_t)row * KC) + tid) = a;

        const float* kR = kptsR + (size_t)b * KM * 2;
        float su = 0.0f;
        for (int m = tid; m < KM; m += 128) su += kR[2 * m];
        s_sc[tid & 127] = su; __syncthreads();
        if (tid < 32) {
            float t = s_sc[tid] + s_sc[tid + 32] + s_sc[tid + 64] + s_sc[tid + 96];
#pragma unroll
            for (int o = 16; o > 0; o >>= 1)
                t += __shfl_xor_sync(0xffffffffu, t, o);
            if (tid == 0) { disp[row] = uL - t * wu; conf[row] = 0.0f; }
        }
    }
}

// ---------------------------------------------------------------------------
extern "C" void kernel_launch(void* const* d_in, const int* in_sizes, int n_in,
                              void* d_out, int out_size)
{
    (void)in_sizes; (void)n_in; (void)out_size;

    const float* nodes_L = (const float*)d_in[0];
    const float* nodes_R = (const float*)d_in[1];
    const float* kpts_L  = (const float*)d_in[2];
    const float* kpts_R  = (const float*)d_in[3];
    const float* Wq = (const float*)d_in[4];
    const float* bq = (const float*)d_in[5];
    const float* Wk = (const float*)d_in[6];
    const float* bk = (const float*)d_in[7];
    const float* Wv = (const float*)d_in[8];
    const float* bv = (const float*)d_in[9];
    const float* Wm = (const float*)d_in[10];
    const float* bm = (const float*)d_in[11];

    float* out      = (float*)d_out;
    float* out_feat = out;
    float* out_disp = out_feat + (size_t)KB * KN * KC;
    float* out_conf = out_disp + (size_t)KB * KN;
    float* out_attn = out_conf + (size_t)KB * KN;

    float *pQ, *pK, *pV, *pMF;
    cudaGetSymbolAddress((void**)&pQ,  g_Q);
    cudaGetSymbolAddress((void**)&pK,  g_K);
    cudaGetSymbolAddress((void**)&pV,  g_V);
    cudaGetSymbolAddress((void**)&pMF, g_MF);

    const int gemm_smem = 4 * ABYTES;   // 73728 bytes
    cudaFuncSetAttribute(gemm_qkv, cudaFuncAttributeMaxDynamicSharedMemorySize,
                         gemm_smem);
    cudaFuncSetAttribute(gemm_out, cudaFuncAttributeMaxDynamicSharedMemorySize,
                         gemm_smem);

    build_bins_kernel<<<KB, 512>>>(kpts_R);

    dim3 qkv_grid(KC / BN, KROWS / BM, 3);
    gemm_qkv<<<qkv_grid, 256, gemm_smem>>>(nodes_L, nodes_R,
                                           Wq, bq, Wk, bk, Wv, bv,
                                           pQ, pK, pV);

    attn_sparse_kernel<<<KROWS, 128>>>(kpts_L, kpts_R,
                                       out_attn, out_disp, out_conf);

    dim3 out_grid(KC / BN, KROWS / BM);
    gemm_out<<<out_grid, 256, gemm_smem>>>(pMF, Wm, bm, out_feat);
}